// round 1
// baseline (speedup 1.0000x reference)
#include <cuda_runtime.h>
#include <cuda_bf16.h>
#include <math.h>

// Problem constants
#define BATCH 2
#define SEQ   4096
#define DM    1024
#define NH    16
#define DH    64
#define L3    3072          // 3*DM
#define ROWS  (BATCH*SEQ)   // 8192

// Scratch (device globals: allocation-free per harness rules)
__device__ float g_qkv[(size_t)ROWS * L3];   // [row][s*1024 + h*64 + d]
__device__ float g_att[(size_t)ROWS * DM];   // attention output, [row][h*64 + d]

// ---------------------------------------------------------------------------
// Tiled SGEMM with bias: C[M,N] = A[M,K] @ B[K,N] + bias[N]
// 128x128 CTA tile, 8x8 per thread (split 4+4), BK=8, 256 threads.
// ---------------------------------------------------------------------------
__global__ __launch_bounds__(256, 2)
void sgemm_bias_kernel(const float* __restrict__ A, const float* __restrict__ B,
                       const float* __restrict__ bias, float* __restrict__ C,
                       int M, int N, int K)
{
    __shared__ float As[8][132];   // [k][m], padded
    __shared__ float Bs[8][128];   // [k][n]

    const int tid = threadIdx.x;
    const int tx  = tid & 15;      // n-group
    const int ty  = tid >> 4;      // m-group
    const int m0  = blockIdx.y * 128;
    const int n0  = blockIdx.x * 128;

    const int am = tid >> 1;          // 0..127
    const int ak = (tid & 1) * 4;     // 0 or 4
    const int bk = tid >> 5;          // 0..7
    const int bn = (tid & 31) * 4;    // 0..124

    const float* Aptr = A + (size_t)(m0 + am) * K + ak;
    const float* Bptr = B + (size_t)bk * N + n0 + bn;

    float acc[8][8];
    #pragma unroll
    for (int i = 0; i < 8; i++)
        #pragma unroll
        for (int j = 0; j < 8; j++) acc[i][j] = 0.0f;

    for (int k0 = 0; k0 < K; k0 += 8) {
        float4 av = *(const float4*)(Aptr + k0);
        float4 bv = *(const float4*)(Bptr + (size_t)k0 * N);
        __syncthreads();
        As[ak + 0][am] = av.x;
        As[ak + 1][am] = av.y;
        As[ak + 2][am] = av.z;
        As[ak + 3][am] = av.w;
        *(float4*)&Bs[bk][bn] = bv;
        __syncthreads();

        #pragma unroll
        for (int k = 0; k < 8; k++) {
            float4 a0 = *(float4*)&As[k][ty * 4];
            float4 a1 = *(float4*)&As[k][64 + ty * 4];
            float4 b0 = *(float4*)&Bs[k][tx * 4];
            float4 b1 = *(float4*)&Bs[k][64 + tx * 4];
            float a[8] = {a0.x, a0.y, a0.z, a0.w, a1.x, a1.y, a1.z, a1.w};
            float b[8] = {b0.x, b0.y, b0.z, b0.w, b1.x, b1.y, b1.z, b1.w};
            #pragma unroll
            for (int i = 0; i < 8; i++)
                #pragma unroll
                for (int j = 0; j < 8; j++)
                    acc[i][j] += a[i] * b[j];
        }
    }

    #pragma unroll
    for (int i = 0; i < 8; i++) {
        int row = m0 + ((i < 4) ? (ty * 4 + i) : (64 + ty * 4 + i - 4));
        #pragma unroll
        for (int j = 0; j < 8; j++) {
            int col = n0 + ((j < 4) ? (tx * 4 + j) : (64 + tx * 4 + j - 4));
            C[(size_t)row * N + col] = acc[i][j] + bias[col];
        }
    }
}

// ---------------------------------------------------------------------------
// RoPE in-place on q (s=0) and k (s=1) slices of g_qkv. theta=500, scale=1.
// One thread per (row, s, h, j<32) pair.
// ---------------------------------------------------------------------------
__global__ void rope_kernel(float* __restrict__ qkv)
{
    int idx = blockIdx.x * 256 + threadIdx.x;     // total = 2^23
    int j = idx & 31;
    int h = (idx >> 5) & 15;
    int s = (idx >> 9) & 1;
    int l = (idx >> 10) & 4095;
    int b = idx >> 22;

    size_t base = ((size_t)(b * SEQ + l)) * L3 + s * 1024 + h * 64 + j;
    float t1 = qkv[base];
    float t2 = qkv[base + 32];

    float p    = powf(500.0f, (float)j * (1.0f / 32.0f));
    float freq = 1.0f / p;
    float ang  = (float)l * freq;
    float sn, cs;
    sincosf(ang, &sn, &cs);

    qkv[base]      = t1 * cs - t2 * sn;
    qkv[base + 32] = t1 * sn + t2 * cs;
}

// ---------------------------------------------------------------------------
// Flash attention (fp32, online softmax). One block per (q-tile=128, h, b).
// BN=64 key tile. 256 threads as 16x16 grid: each thread owns 8 query rows
// (ty*8..+7) and 4 strided columns (tx, tx+16, tx+32, tx+48) for both the
// S fragment (keys) and the O fragment (head dims). Strided columns keep all
// shared-memory fragment loads conflict-free or 2-way at worst.
// ---------------------------------------------------------------------------
#define FBM 128
#define FBN 64
#define KSTR 68   // padded K-tile row stride (keeps float4 alignment, kills conflicts)
#define FLASH_SMEM ((FBM*DH + FBN*KSTR + FBN*DH + FBM*FBN) * sizeof(float))

__global__ __launch_bounds__(256, 2)
void flash_kernel(const float* __restrict__ qkv, float* __restrict__ oatt)
{
    extern __shared__ float sm[];
    float* Qs = sm;                    // [128][64]
    float* Ks = Qs + FBM * DH;         // [64][68]  (pre-scaled by 1/8)
    float* Vs = Ks + FBN * KSTR;       // [64][64]
    float* Ps = Vs + FBN * DH;         // [128][64]

    const int tid = threadIdx.x;
    const int tx  = tid & 15;
    const int ty  = tid >> 4;
    const int qt  = blockIdx.x;
    const int h   = blockIdx.y;
    const int b   = blockIdx.z;

    const size_t rowbase = (size_t)b * SEQ;
    const int qoff = h * 64;
    const int koff = 1024 + h * 64;
    const int voff = 2048 + h * 64;

    // Load Q tile
    #pragma unroll
    for (int i = 0; i < 8; i++) {
        int idx = tid + i * 256;
        int m   = idx >> 4;
        int d4  = (idx & 15) * 4;
        float4 v = *(const float4*)(qkv + (rowbase + qt * FBM + m) * L3 + qoff + d4);
        *(float4*)&Qs[m * DH + d4] = v;
    }

    float mrow[8], lrow[8], o[8][4];
    #pragma unroll
    for (int r = 0; r < 8; r++) {
        mrow[r] = -INFINITY;
        lrow[r] = 0.0f;
        #pragma unroll
        for (int c = 0; c < 4; c++) o[r][c] = 0.0f;
    }

    for (int t = 0; t < SEQ / FBN; t++) {
        __syncthreads();   // previous iteration done with Ks/Vs/Ps
        // Load K (pre-scaled) and V tiles
        #pragma unroll
        for (int i = 0; i < 4; i++) {
            int idx = tid + i * 256;            // 0..1023
            int n   = idx >> 4;
            int d4  = (idx & 15) * 4;
            size_t gr = (rowbase + t * FBN + n) * L3;
            float4 kv = *(const float4*)(qkv + gr + koff + d4);
            kv.x *= 0.125f; kv.y *= 0.125f; kv.z *= 0.125f; kv.w *= 0.125f;
            *(float4*)&Ks[n * KSTR + d4] = kv;
            float4 vv = *(const float4*)(qkv + gr + voff + d4);
            *(float4*)&Vs[n * DH + d4] = vv;
        }
        __syncthreads();

        // S = Q @ K^T (scaled)
        float s[8][4];
        #pragma unroll
        for (int r = 0; r < 8; r++)
            #pragma unroll
            for (int c = 0; c < 4; c++) s[r][c] = 0.0f;

        #pragma unroll 2
        for (int d4 = 0; d4 < DH; d4 += 4) {
            float4 kf[4];
            #pragma unroll
            for (int c = 0; c < 4; c++)
                kf[c] = *(float4*)&Ks[(tx + 16 * c) * KSTR + d4];
            #pragma unroll
            for (int r = 0; r < 8; r++) {
                float4 qf = *(float4*)&Qs[(ty * 8 + r) * DH + d4];
                #pragma unroll
                for (int c = 0; c < 4; c++) {
                    s[r][c] += qf.x * kf[c].x;
                    s[r][c] += qf.y * kf[c].y;
                    s[r][c] += qf.z * kf[c].z;
                    s[r][c] += qf.w * kf[c].w;
                }
            }
        }

        // Online softmax update; stage P into shared
        #pragma unroll
        for (int r = 0; r < 8; r++) {
            float mx = fmaxf(fmaxf(s[r][0], s[r][1]), fmaxf(s[r][2], s[r][3]));
            #pragma unroll
            for (int off = 8; off > 0; off >>= 1)
                mx = fmaxf(mx, __shfl_xor_sync(0xffffffffu, mx, off));
            float mnew  = fmaxf(mrow[r], mx);
            float alpha = __expf(mrow[r] - mnew);
            float ps = 0.0f;
            #pragma unroll
            for (int c = 0; c < 4; c++) {
                float p = __expf(s[r][c] - mnew);
                s[r][c] = p;
                ps += p;
            }
            #pragma unroll
            for (int off = 8; off > 0; off >>= 1)
                ps += __shfl_xor_sync(0xffffffffu, ps, off);
            lrow[r] = lrow[r] * alpha + ps;
            mrow[r] = mnew;
            #pragma unroll
            for (int c = 0; c < 4; c++) o[r][c] *= alpha;
            #pragma unroll
            for (int c = 0; c < 4; c++)
                Ps[(ty * 8 + r) * FBN + tx + 16 * c] = s[r][c];
        }
        __syncthreads();

        // O += P @ V
        #pragma unroll 2
        for (int n4 = 0; n4 < FBN; n4 += 4) {
            float vf[4][4];
            #pragma unroll
            for (int jj = 0; jj < 4; jj++)
                #pragma unroll
                for (int c = 0; c < 4; c++)
                    vf[jj][c] = Vs[(n4 + jj) * DH + tx + 16 * c];
            #pragma unroll
            for (int r = 0; r < 8; r++) {
                float4 pf = *(float4*)&Ps[(ty * 8 + r) * FBN + n4];
                float pa[4] = {pf.x, pf.y, pf.z, pf.w};
                #pragma unroll
                for (int jj = 0; jj < 4; jj++)
                    #pragma unroll
                    for (int c = 0; c < 4; c++)
                        o[r][c] += pa[jj] * vf[jj][c];
            }
        }
    }

    // Normalize and write to g_att in [row][h*64 + d] layout
    #pragma unroll
    for (int r = 0; r < 8; r++) {
        float inv = 1.0f / lrow[r];
        int m = qt * FBM + ty * 8 + r;
        size_t orow = (rowbase + m) * DM + h * 64;
        #pragma unroll
        for (int c = 0; c < 4; c++)
            oatt[orow + tx + 16 * c] = o[r][c] * inv;
    }
}

// ---------------------------------------------------------------------------
// Launcher
// ---------------------------------------------------------------------------
extern "C" void kernel_launch(void* const* d_in, const int* in_sizes, int n_in,
                              void* d_out, int out_size)
{
    const float* x     = (const float*)d_in[0];
    const float* w_qkv = (const float*)d_in[1];
    const float* b_qkv = (const float*)d_in[2];
    const float* w_out = (const float*)d_in[3];
    const float* b_out = (const float*)d_in[4];
    float* out = (float*)d_out;

    float *qkv_s, *att_s;
    cudaGetSymbolAddress((void**)&qkv_s, g_qkv);
    cudaGetSymbolAddress((void**)&att_s, g_att);

    cudaFuncSetAttribute(flash_kernel, cudaFuncAttributeMaxDynamicSharedMemorySize,
                         (int)FLASH_SMEM);

    // QKV projection: [8192,1024] @ [1024,3072] + b
    sgemm_bias_kernel<<<dim3(L3 / 128, ROWS / 128), 256>>>(
        x, w_qkv, b_qkv, qkv_s, ROWS, L3, DM);

    // RoPE on q and k slices (in place)
    rope_kernel<<<(BATCH * SEQ * 2 * NH * 32) / 256, 256>>>(qkv_s);

    // Flash attention -> g_att
    flash_kernel<<<dim3(SEQ / FBM, NH, BATCH), 256, FLASH_SMEM>>>(qkv_s, att_s);

    // Output projection: [8192,1024] @ [1024,1024] + b
    sgemm_bias_kernel<<<dim3(DM / 128, ROWS / 128), 256>>>(
        att_s, w_out, b_out, out, ROWS, DM, DM);
}

// round 2
// speedup vs baseline: 2.0002x; 2.0002x over previous
#include <cuda_runtime.h>
#include <cuda_bf16.h>
#include <math.h>
#include <stdint.h>

#define BATCH 2
#define SEQ   4096
#define DM    1024
#define NH    16
#define DH    64
#define L3    3072
#define ROWS  (BATCH*SEQ)

// Scratch (device globals: allocation-free per harness rules)
__device__ float g_qkv[(size_t)ROWS * L3];   // fp32 qkv, [row][s*1024 + h*64 + d]
__device__ float g_att[(size_t)ROWS * DM];   // fp32 attention output

// ---------------------------------------------------------------------------
// Helpers: bf16 split-2 and mma.sync wrapper
// ---------------------------------------------------------------------------
__device__ __forceinline__ uint32_t pack2(__nv_bfloat16 a, __nv_bfloat16 b) {
    __nv_bfloat162 t; t.x = a; t.y = b;
    return *reinterpret_cast<uint32_t*>(&t);
}

__device__ __forceinline__ void split1(float f, __nv_bfloat16& h, __nv_bfloat16& l) {
    h = __float2bfloat16_rn(f);
    l = __float2bfloat16_rn(f - __bfloat162float(h));
}

union B4U { __nv_bfloat16 b[4]; uint2 u; };

__device__ __forceinline__ void split4_store(float4 v, __nv_bfloat16* ph, __nv_bfloat16* pl) {
    B4U H, L;
    split1(v.x, H.b[0], L.b[0]);
    split1(v.y, H.b[1], L.b[1]);
    split1(v.z, H.b[2], L.b[2]);
    split1(v.w, H.b[3], L.b[3]);
    *reinterpret_cast<uint2*>(ph) = H.u;
    *reinterpret_cast<uint2*>(pl) = L.u;
}

__device__ __forceinline__ void mma_bf16(float c[4],
                                         uint32_t a0, uint32_t a1, uint32_t a2, uint32_t a3,
                                         uint32_t b0, uint32_t b1) {
    asm volatile(
        "mma.sync.aligned.m16n8k16.row.col.f32.bf16.bf16.f32 "
        "{%0,%1,%2,%3}, {%4,%5,%6,%7}, {%8,%9}, {%0,%1,%2,%3};\n"
        : "+f"(c[0]), "+f"(c[1]), "+f"(c[2]), "+f"(c[3])
        : "r"(a0), "r"(a1), "r"(a2), "r"(a3), "r"(b0), "r"(b1));
}

// ---------------------------------------------------------------------------
// Split-bf16 GEMM + bias: C[M,N] = A[M,K] @ B[K,N] + bias
// CTA 128x128, BK=32, 8 warps (2m x 4n), warp tile 64x32 via m16n8k16.
// fp32 -> (hi,lo) bf16 conversion happens during global->smem staging.
// 3 MMAs per tile: Ah*Bh + Ah*Bl + Al*Bh.
// ---------------------------------------------------------------------------
#define AKS 40    // A smem stride (bf16 elems)
#define BNS 136   // B smem stride (bf16 elems)

__global__ __launch_bounds__(256, 2)
void gemm_mma(const float* __restrict__ A, const float* __restrict__ B,
              const float* __restrict__ bias, float* __restrict__ C,
              int M, int N, int K)
{
    __shared__ __nv_bfloat16 Ah[128 * AKS], Al[128 * AKS];
    __shared__ __nv_bfloat16 Bh[32 * BNS],  Bl[32 * BNS];

    const int tid  = threadIdx.x;
    const int lane = tid & 31;
    const int wm   = (tid >> 5) & 1;
    const int wn   = tid >> 6;
    const int m0   = blockIdx.y * 128;
    const int n0   = blockIdx.x * 128;

    float acc[4][4][4];
    #pragma unroll
    for (int i = 0; i < 4; i++)
        #pragma unroll
        for (int j = 0; j < 4; j++)
            #pragma unroll
            for (int k = 0; k < 4; k++) acc[i][j][k] = 0.0f;

    float4 pa[4], pb[4];
    #pragma unroll
    for (int i = 0; i < 4; i++) {
        int idx = i * 256 + tid;
        pa[i] = *(const float4*)(A + (size_t)(m0 + (idx >> 3)) * K + (idx & 7) * 4);
        pb[i] = *(const float4*)(B + (size_t)(idx >> 5) * N + n0 + (idx & 31) * 4);
    }

    for (int k0 = 0; k0 < K; k0 += 32) {
        __syncthreads();
        #pragma unroll
        for (int i = 0; i < 4; i++) {
            int idx = i * 256 + tid;
            int ar = idx >> 3, ak = (idx & 7) * 4;
            split4_store(pa[i], &Ah[ar * AKS + ak], &Al[ar * AKS + ak]);
            int bk = idx >> 5, bn = (idx & 31) * 4;
            split4_store(pb[i], &Bh[bk * BNS + bn], &Bl[bk * BNS + bn]);
        }
        __syncthreads();
        if (k0 + 32 < K) {
            #pragma unroll
            for (int i = 0; i < 4; i++) {
                int idx = i * 256 + tid;
                pa[i] = *(const float4*)(A + (size_t)(m0 + (idx >> 3)) * K + k0 + 32 + (idx & 7) * 4);
                pb[i] = *(const float4*)(B + (size_t)(k0 + 32 + (idx >> 5)) * N + n0 + (idx & 31) * 4);
            }
        }

        #pragma unroll
        for (int ks = 0; ks < 2; ks++) {
            const int kb   = ks * 16 + (lane & 3) * 2;
            const int arow = wm * 64 + (lane >> 2);
            uint32_t af[4][4];

            // pass 1: Ah*Bh + Ah*Bl
            #pragma unroll
            for (int mt = 0; mt < 4; mt++) {
                const __nv_bfloat16* p = &Ah[(arow + mt * 16) * AKS + kb];
                af[mt][0] = *(const uint32_t*)p;
                af[mt][1] = *(const uint32_t*)(p + 8 * AKS);
                af[mt][2] = *(const uint32_t*)(p + 8);
                af[mt][3] = *(const uint32_t*)(p + 8 * AKS + 8);
            }
            #pragma unroll
            for (int nt = 0; nt < 4; nt++) {
                const int col = wn * 32 + nt * 8 + (lane >> 2);
                const int kr  = ks * 16 + (lane & 3) * 2;
                uint32_t bh0 = pack2(Bh[kr * BNS + col],       Bh[(kr + 1) * BNS + col]);
                uint32_t bh1 = pack2(Bh[(kr + 8) * BNS + col], Bh[(kr + 9) * BNS + col]);
                uint32_t bl0 = pack2(Bl[kr * BNS + col],       Bl[(kr + 1) * BNS + col]);
                uint32_t bl1 = pack2(Bl[(kr + 8) * BNS + col], Bl[(kr + 9) * BNS + col]);
                #pragma unroll
                for (int mt = 0; mt < 4; mt++) {
                    mma_bf16(acc[mt][nt], af[mt][0], af[mt][1], af[mt][2], af[mt][3], bh0, bh1);
                    mma_bf16(acc[mt][nt], af[mt][0], af[mt][1], af[mt][2], af[mt][3], bl0, bl1);
                }
            }
            // pass 2: Al*Bh
            #pragma unroll
            for (int mt = 0; mt < 4; mt++) {
                const __nv_bfloat16* p = &Al[(arow + mt * 16) * AKS + kb];
                af[mt][0] = *(const uint32_t*)p;
                af[mt][1] = *(const uint32_t*)(p + 8 * AKS);
                af[mt][2] = *(const uint32_t*)(p + 8);
                af[mt][3] = *(const uint32_t*)(p + 8 * AKS + 8);
            }
            #pragma unroll
            for (int nt = 0; nt < 4; nt++) {
                const int col = wn * 32 + nt * 8 + (lane >> 2);
                const int kr  = ks * 16 + (lane & 3) * 2;
                uint32_t bh0 = pack2(Bh[kr * BNS + col],       Bh[(kr + 1) * BNS + col]);
                uint32_t bh1 = pack2(Bh[(kr + 8) * BNS + col], Bh[(kr + 9) * BNS + col]);
                #pragma unroll
                for (int mt = 0; mt < 4; mt++)
                    mma_bf16(acc[mt][nt], af[mt][0], af[mt][1], af[mt][2], af[mt][3], bh0, bh1);
            }
        }
    }

    #pragma unroll
    for (int nt = 0; nt < 4; nt++) {
        int col = n0 + wn * 32 + nt * 8 + (lane & 3) * 2;
        float2 bs = *(const float2*)&bias[col];
        #pragma unroll
        for (int mt = 0; mt < 4; mt++) {
            int r = m0 + wm * 64 + mt * 16 + (lane >> 2);
            float2 v0 = { acc[mt][nt][0] + bs.x, acc[mt][nt][1] + bs.y };
            float2 v1 = { acc[mt][nt][2] + bs.x, acc[mt][nt][3] + bs.y };
            *(float2*)&C[(size_t)r * N + col]       = v0;
            *(float2*)&C[(size_t)(r + 8) * N + col] = v1;
        }
    }
}

// ---------------------------------------------------------------------------
// RoPE in-place on q/k slices of g_qkv (fp32). theta=500, scale=1.
// ---------------------------------------------------------------------------
__global__ void rope_kernel(float* __restrict__ qkv)
{
    int idx = blockIdx.x * 256 + threadIdx.x;
    int j = idx & 31;
    int h = (idx >> 5) & 15;
    int s = (idx >> 9) & 1;
    int l = (idx >> 10) & 4095;
    int b = idx >> 22;

    size_t base = ((size_t)(b * SEQ + l)) * L3 + s * 1024 + h * 64 + j;
    float t1 = qkv[base];
    float t2 = qkv[base + 32];

    float freq = 1.0f / powf(500.0f, (float)j * (1.0f / 32.0f));
    float ang  = (float)l * freq;
    float sn, cs;
    sincosf(ang, &sn, &cs);

    qkv[base]      = t1 * cs - t2 * sn;
    qkv[base + 32] = t1 * sn + t2 * cs;
}

// ---------------------------------------------------------------------------
// Flash attention with split-bf16 mma.sync.
// CTA: 128 q-rows x (64-key tiles), 8 warps each owning 16 q-rows.
// Q pre-scaled by 1/8 and split once; K/V split per tile (V stored d-major).
// S via 3-MMA QK^T; online softmax on C-fragments; P re-packed in registers
// into A-fragment layout (hi+lo); PV via 3-MMA accumulating into O.
// ---------------------------------------------------------------------------
#define FSTR 72
#define FLASH_SMEM ((128*FSTR*2 + 64*FSTR*4) * sizeof(__nv_bfloat16))  // 73728 B

__global__ __launch_bounds__(256, 2)
void flash_mma(const float* __restrict__ qkv, float* __restrict__ oatt)
{
    extern __shared__ __nv_bfloat16 smf[];
    __nv_bfloat16* Qh = smf;
    __nv_bfloat16* Ql = Qh + 128 * FSTR;
    __nv_bfloat16* Kh = Ql + 128 * FSTR;
    __nv_bfloat16* Kl = Kh + 64 * FSTR;
    __nv_bfloat16* Vh = Kl + 64 * FSTR;   // d-major: [d][key]
    __nv_bfloat16* Vl = Vh + 64 * FSTR;

    const int tid  = threadIdx.x;
    const int lane = tid & 31;
    const int wid  = tid >> 5;
    const int qt   = blockIdx.x;
    const int h    = blockIdx.y;
    const int b    = blockIdx.z;
    const size_t rowbase = (size_t)b * SEQ;

    const float* Qg = qkv + (rowbase + qt * 128) * L3 + h * 64;
    const float* Kg = qkv + rowbase * L3 + 1024 + h * 64;
    const float* Vg = qkv + rowbase * L3 + 2048 + h * 64;

    // Load + split Q once (pre-scaled by 1/sqrt(Dh) = 1/8)
    #pragma unroll
    for (int i = 0; i < 8; i++) {
        int idx = i * 256 + tid;
        int r = idx >> 4, d4 = (idx & 15) * 4;
        float4 v = *(const float4*)(Qg + (size_t)r * L3 + d4);
        v.x *= 0.125f; v.y *= 0.125f; v.z *= 0.125f; v.w *= 0.125f;
        split4_store(v, &Qh[r * FSTR + d4], &Ql[r * FSTR + d4]);
    }

    float s[8][4], o[8][4];
    float m0r = -INFINITY, m1r = -INFINITY, l0r = 0.0f, l1r = 0.0f;
    #pragma unroll
    for (int i = 0; i < 8; i++)
        #pragma unroll
        for (int j = 0; j < 4; j++) o[i][j] = 0.0f;

    const int r0   = lane >> 2;
    const int kq   = (lane & 3) * 2;
    const int qrow = wid * 16 + r0;

    for (int t = 0; t < SEQ / 64; t++) {
        __syncthreads();
        // Load + split K and V tiles (V transposed to d-major)
        #pragma unroll
        for (int i = 0; i < 4; i++) {
            int idx = i * 256 + tid;
            int r = idx >> 4, d4 = (idx & 15) * 4;
            size_t go = (size_t)(t * 64 + r) * L3 + d4;
            float4 kv = *(const float4*)(Kg + go);
            split4_store(kv, &Kh[r * FSTR + d4], &Kl[r * FSTR + d4]);
            float4 vv = *(const float4*)(Vg + go);
            float f[4] = { vv.x, vv.y, vv.z, vv.w };
            #pragma unroll
            for (int j = 0; j < 4; j++) {
                __nv_bfloat16 hh = __float2bfloat16_rn(f[j]);
                Vh[(d4 + j) * FSTR + r] = hh;
                Vl[(d4 + j) * FSTR + r] = __float2bfloat16_rn(f[j] - __bfloat162float(hh));
            }
        }
        __syncthreads();

        // S = Q @ K^T (3-MMA split)
        #pragma unroll
        for (int i = 0; i < 8; i++)
            #pragma unroll
            for (int j = 0; j < 4; j++) s[i][j] = 0.0f;

        #pragma unroll
        for (int ks = 0; ks < 4; ks++) {
            const __nv_bfloat16* qp  = &Qh[qrow * FSTR + ks * 16 + kq];
            const __nv_bfloat16* qlp = &Ql[qrow * FSTR + ks * 16 + kq];
            uint32_t qh0 = *(const uint32_t*)qp;
            uint32_t qh1 = *(const uint32_t*)(qp + 8 * FSTR);
            uint32_t qh2 = *(const uint32_t*)(qp + 8);
            uint32_t qh3 = *(const uint32_t*)(qp + 8 * FSTR + 8);
            uint32_t ql0 = *(const uint32_t*)qlp;
            uint32_t ql1 = *(const uint32_t*)(qlp + 8 * FSTR);
            uint32_t ql2 = *(const uint32_t*)(qlp + 8);
            uint32_t ql3 = *(const uint32_t*)(qlp + 8 * FSTR + 8);
            #pragma unroll
            for (int nt = 0; nt < 8; nt++) {
                const __nv_bfloat16* kp  = &Kh[(nt * 8 + r0) * FSTR + ks * 16 + kq];
                const __nv_bfloat16* klp = &Kl[(nt * 8 + r0) * FSTR + ks * 16 + kq];
                uint32_t bh0 = *(const uint32_t*)kp;
                uint32_t bh1 = *(const uint32_t*)(kp + 8);
                uint32_t bl0 = *(const uint32_t*)klp;
                uint32_t bl1 = *(const uint32_t*)(klp + 8);
                mma_bf16(s[nt], qh0, qh1, qh2, qh3, bh0, bh1);
                mma_bf16(s[nt], qh0, qh1, qh2, qh3, bl0, bl1);
                mma_bf16(s[nt], ql0, ql1, ql2, ql3, bh0, bh1);
            }
        }

        // Online softmax on fragments (row r owned by a lane quad)
        float mx0 = -INFINITY, mx1 = -INFINITY;
        #pragma unroll
        for (int nt = 0; nt < 8; nt++) {
            mx0 = fmaxf(mx0, fmaxf(s[nt][0], s[nt][1]));
            mx1 = fmaxf(mx1, fmaxf(s[nt][2], s[nt][3]));
        }
        mx0 = fmaxf(mx0, __shfl_xor_sync(0xffffffffu, mx0, 1));
        mx0 = fmaxf(mx0, __shfl_xor_sync(0xffffffffu, mx0, 2));
        mx1 = fmaxf(mx1, __shfl_xor_sync(0xffffffffu, mx1, 1));
        mx1 = fmaxf(mx1, __shfl_xor_sync(0xffffffffu, mx1, 2));
        float mn0 = fmaxf(m0r, mx0), mn1 = fmaxf(m1r, mx1);
        float a0 = __expf(m0r - mn0), a1 = __expf(m1r - mn1);
        float sum0 = 0.0f, sum1 = 0.0f;
        #pragma unroll
        for (int nt = 0; nt < 8; nt++) {
            s[nt][0] = __expf(s[nt][0] - mn0); sum0 += s[nt][0];
            s[nt][1] = __expf(s[nt][1] - mn0); sum0 += s[nt][1];
            s[nt][2] = __expf(s[nt][2] - mn1); sum1 += s[nt][2];
            s[nt][3] = __expf(s[nt][3] - mn1); sum1 += s[nt][3];
        }
        sum0 += __shfl_xor_sync(0xffffffffu, sum0, 1);
        sum0 += __shfl_xor_sync(0xffffffffu, sum0, 2);
        sum1 += __shfl_xor_sync(0xffffffffu, sum1, 1);
        sum1 += __shfl_xor_sync(0xffffffffu, sum1, 2);
        l0r = l0r * a0 + sum0;  l1r = l1r * a1 + sum1;
        m0r = mn0;              m1r = mn1;
        #pragma unroll
        for (int dt = 0; dt < 8; dt++) {
            o[dt][0] *= a0; o[dt][1] *= a0;
            o[dt][2] *= a1; o[dt][3] *= a1;
        }

        // O += P @ V : re-pack P (C-frag -> A-frag identity) with hi/lo split
        #pragma unroll
        for (int kt = 0; kt < 4; kt++) {
            __nv_bfloat16 h00, h01, h02, h03, h10, h11, h12, h13;
            __nv_bfloat16 g00, g01, g02, g03, g10, g11, g12, g13;
            split1(s[2*kt][0],   h00, g00);
            split1(s[2*kt][1],   h01, g01);
            split1(s[2*kt][2],   h02, g02);
            split1(s[2*kt][3],   h03, g03);
            split1(s[2*kt+1][0], h10, g10);
            split1(s[2*kt+1][1], h11, g11);
            split1(s[2*kt+1][2], h12, g12);
            split1(s[2*kt+1][3], h13, g13);
            uint32_t ah0 = pack2(h00, h01), ah1 = pack2(h02, h03);
            uint32_t ah2 = pack2(h10, h11), ah3 = pack2(h12, h13);
            uint32_t au0 = pack2(g00, g01), au1 = pack2(g02, g03);
            uint32_t au2 = pack2(g10, g11), au3 = pack2(g12, g13);
            #pragma unroll
            for (int dt = 0; dt < 8; dt++) {
                const __nv_bfloat16* vp  = &Vh[(dt * 8 + r0) * FSTR + kt * 16 + kq];
                const __nv_bfloat16* vlp = &Vl[(dt * 8 + r0) * FSTR + kt * 16 + kq];
                uint32_t bh0 = *(const uint32_t*)vp;
                uint32_t bh1 = *(const uint32_t*)(vp + 8);
                uint32_t bl0 = *(const uint32_t*)vlp;
                uint32_t bl1 = *(const uint32_t*)(vlp + 8);
                mma_bf16(o[dt], ah0, ah1, ah2, ah3, bh0, bh1);
                mma_bf16(o[dt], ah0, ah1, ah2, ah3, bl0, bl1);
                mma_bf16(o[dt], au0, au1, au2, au3, bh0, bh1);
            }
        }
    }

    // Epilogue: normalize, write fp32
    float inv0 = 1.0f / l0r, inv1 = 1.0f / l1r;
    const size_t row0 = rowbase + (size_t)qt * 128 + qrow;
    #pragma unroll
    for (int dt = 0; dt < 8; dt++) {
        int col = h * 64 + dt * 8 + kq;
        float2 v0 = { o[dt][0] * inv0, o[dt][1] * inv0 };
        float2 v1 = { o[dt][2] * inv1, o[dt][3] * inv1 };
        *(float2*)&oatt[row0 * DM + col]       = v0;
        *(float2*)&oatt[(row0 + 8) * DM + col] = v1;
    }
}

// ---------------------------------------------------------------------------
// Launcher
// ---------------------------------------------------------------------------
extern "C" void kernel_launch(void* const* d_in, const int* in_sizes, int n_in,
                              void* d_out, int out_size)
{
    const float* x     = (const float*)d_in[0];
    const float* w_qkv = (const float*)d_in[1];
    const float* b_qkv = (const float*)d_in[2];
    const float* w_out = (const float*)d_in[3];
    const float* b_out = (const float*)d_in[4];
    float* out = (float*)d_out;

    float *qkv_s, *att_s;
    cudaGetSymbolAddress((void**)&qkv_s, g_qkv);
    cudaGetSymbolAddress((void**)&att_s, g_att);

    cudaFuncSetAttribute(flash_mma, cudaFuncAttributeMaxDynamicSharedMemorySize,
                         (int)FLASH_SMEM);

    // QKV projection
    gemm_mma<<<dim3(L3 / 128, ROWS / 128), 256>>>(x, w_qkv, b_qkv, qkv_s, ROWS, L3, DM);

    // RoPE (fp32, in place)
    rope_kernel<<<(BATCH * SEQ * 2 * NH * 32) / 256, 256>>>(qkv_s);

    // Flash attention
    flash_mma<<<dim3(SEQ / 128, NH, BATCH), 256, FLASH_SMEM>>>(qkv_s, att_s);

    // Output projection
    gemm_mma<<<dim3(DM / 128, ROWS / 128), 256>>>(att_s, w_out, b_out, out, ROWS, DM, DM);
}

// round 3
// speedup vs baseline: 2.0931x; 1.0465x over previous
#include <cuda_runtime.h>
#include <cuda_bf16.h>
#include <math.h>
#include <stdint.h>

#define BATCH 2
#define SEQ   4096
#define DM    1024
#define NH    16
#define DH    64
#define L3    3072
#define ROWS  (BATCH*SEQ)

// ---------------- device scratch (allocation-free) ----------------
__device__ float g_qkv[(size_t)ROWS * L3];                     // fp32 qkv gemm output
__device__ __nv_bfloat16 g_xh[(size_t)ROWS*DM],  g_xl[(size_t)ROWS*DM];
__device__ __nv_bfloat16 g_wqh[(size_t)DM*L3],   g_wql[(size_t)DM*L3];   // w_qkv^T [3072][1024]
__device__ __nv_bfloat16 g_woh[(size_t)DM*DM],   g_wol[(size_t)DM*DM];   // w_out^T [1024][1024]
__device__ __nv_bfloat16 g_Qh[(size_t)ROWS*DM],  g_Ql[(size_t)ROWS*DM];  // [b][h][l][64], pre-scaled
__device__ __nv_bfloat16 g_Kh[(size_t)ROWS*DM],  g_Kl[(size_t)ROWS*DM];  // [b][h][l][64]
__device__ __nv_bfloat16 g_Vh[(size_t)ROWS*DM],  g_Vl[(size_t)ROWS*DM];  // [b][h][d][SEQ]
__device__ __nv_bfloat16 g_ath[(size_t)ROWS*DM], g_atl[(size_t)ROWS*DM]; // attention out

// ---------------- helpers ----------------
__device__ __forceinline__ uint32_t pack2(__nv_bfloat16 a, __nv_bfloat16 b) {
    __nv_bfloat162 t; t.x = a; t.y = b;
    return *reinterpret_cast<uint32_t*>(&t);
}
__device__ __forceinline__ void split1(float f, __nv_bfloat16& h, __nv_bfloat16& l) {
    h = __float2bfloat16_rn(f);
    l = __float2bfloat16_rn(f - __bfloat162float(h));
}
__device__ __forceinline__ void split_pack2(float f0, float f1, uint32_t& h, uint32_t& l) {
    __nv_bfloat16 h0, l0, h1, l1;
    split1(f0, h0, l0); split1(f1, h1, l1);
    h = pack2(h0, h1); l = pack2(l0, l1);
}
__device__ __forceinline__ void mma_bf16(float c[4],
                                         uint32_t a0, uint32_t a1, uint32_t a2, uint32_t a3,
                                         uint32_t b0, uint32_t b1) {
    asm volatile(
        "mma.sync.aligned.m16n8k16.row.col.f32.bf16.bf16.f32 "
        "{%0,%1,%2,%3}, {%4,%5,%6,%7}, {%8,%9}, {%0,%1,%2,%3};\n"
        : "+f"(c[0]), "+f"(c[1]), "+f"(c[2]), "+f"(c[3])
        : "r"(a0), "r"(a1), "r"(a2), "r"(a3), "r"(b0), "r"(b1));
}
#define LDSM4(r0,r1,r2,r3,addr) \
    asm volatile("ldmatrix.sync.aligned.m8n8.x4.shared.b16 {%0,%1,%2,%3}, [%4];" \
                 : "=r"(r0),"=r"(r1),"=r"(r2),"=r"(r3) : "r"(addr))
#define CP16(s,g)  asm volatile("cp.async.cg.shared.global [%0], [%1], 16;" :: "r"(s), "l"(g))
#define CPCOMMIT() asm volatile("cp.async.commit_group;" ::: "memory")
#define CPWAIT1()  asm volatile("cp.async.wait_group 1;" ::: "memory")

// ---------------------------------------------------------------------------
// prep: transpose + split weights:  W[K][N] fp32  ->  WT_h/l[N][K] bf16
// ---------------------------------------------------------------------------
__global__ void prep_wT(const float* __restrict__ W,
                        __nv_bfloat16* __restrict__ WTh, __nv_bfloat16* __restrict__ WTl,
                        int K, int N)
{
    __shared__ float t[32][33];
    const int tid = threadIdx.x;
    const int n0 = blockIdx.x * 32, k0 = blockIdx.y * 32;
    #pragma unroll
    for (int i = 0; i < 4; i++) {
        int idx = i * 256 + tid;
        int r = idx >> 5, c = idx & 31;
        t[r][c] = W[(size_t)(k0 + r) * N + n0 + c];
    }
    __syncthreads();
    uint32_t* oh = (uint32_t*)WTh;
    uint32_t* ol = (uint32_t*)WTl;
    #pragma unroll
    for (int i = 0; i < 2; i++) {
        int idx = i * 256 + tid;
        int n = idx >> 4, kp = idx & 15;
        uint32_t h, l;
        split_pack2(t[2*kp][n], t[2*kp+1][n], h, l);
        size_t o = ((size_t)(n0 + n) * K + k0) / 2 + kp;
        oh[o] = h; ol[o] = l;
    }
}

// ---------------------------------------------------------------------------
// prep: split x (row-major, no transpose)
// ---------------------------------------------------------------------------
__global__ void prep_x(const float* __restrict__ x,
                       __nv_bfloat16* __restrict__ xh, __nv_bfloat16* __restrict__ xl)
{
    size_t i = (size_t)blockIdx.x * 256 + threadIdx.x;
    float2 v = ((const float2*)x)[i];
    uint32_t h, l;
    split_pack2(v.x, v.y, h, l);
    ((uint32_t*)xh)[i] = h;
    ((uint32_t*)xl)[i] = l;
}

// ---------------------------------------------------------------------------
// prep: RoPE + split qkv.  Q scaled by 1/8.  V transposed to [b][h][d][SEQ].
// grid (SEQ/64, NH, BATCH), 256 threads.
// ---------------------------------------------------------------------------
__global__ void prep_qkv(const float* __restrict__ qkv)
{
    __shared__ float vs[64][65];
    const int tid = threadIdx.x;
    const int lt = blockIdx.x, h = blockIdx.y, b = blockIdx.z;
    const size_t rowg = (size_t)b * SEQ + lt * 64;
    const size_t bh = (size_t)b * NH + h;

    uint32_t* Qh32 = (uint32_t*)g_Qh; uint32_t* Ql32 = (uint32_t*)g_Ql;
    uint32_t* Kh32 = (uint32_t*)g_Kh; uint32_t* Kl32 = (uint32_t*)g_Kl;
    uint32_t* Vh32 = (uint32_t*)g_Vh; uint32_t* Vl32 = (uint32_t*)g_Vl;

    #pragma unroll
    for (int i = 0; i < 4; i++) {
        int idx = i * 256 + tid;          // 0..1023
        int r = idx >> 4;                 // row in tile
        int j = idx & 15;                 // d-pair (d0 = 2j < 32)
        int l = lt * 64 + r;
        const float* row = qkv + (rowg + r) * L3;
        float f0 = powf(500.0f, -(float)(2*j)     * (1.0f/32.0f));
        float f1 = powf(500.0f, -(float)(2*j + 1) * (1.0f/32.0f));
        float s0, c0, s1, c1;
        sincosf((float)l * f0, &s0, &c0);
        sincosf((float)l * f1, &s1, &c1);
        size_t ob = (bh * SEQ + l) * 32;  // u32 row base (64 bf16 = 32 u32)
        // Q (scaled)
        {
            const float* q = row + h * 64;
            float t1a = q[2*j], t1b = q[2*j+1], t2a = q[2*j+32], t2b = q[2*j+33];
            uint32_t hh, ll;
            split_pack2((t1a*c0 - t2a*s0) * 0.125f, (t1b*c1 - t2b*s1) * 0.125f, hh, ll);
            Qh32[ob + j] = hh;      Ql32[ob + j] = ll;
            split_pack2((t1a*s0 + t2a*c0) * 0.125f, (t1b*s1 + t2b*c1) * 0.125f, hh, ll);
            Qh32[ob + 16 + j] = hh; Ql32[ob + 16 + j] = ll;
        }
        // K
        {
            const float* k = row + 1024 + h * 64;
            float t1a = k[2*j], t1b = k[2*j+1], t2a = k[2*j+32], t2b = k[2*j+33];
            uint32_t hh, ll;
            split_pack2(t1a*c0 - t2a*s0, t1b*c1 - t2b*s1, hh, ll);
            Kh32[ob + j] = hh;      Kl32[ob + j] = ll;
            split_pack2(t1a*s0 + t2a*c0, t1b*s1 + t2b*c1, hh, ll);
            Kh32[ob + 16 + j] = hh; Kl32[ob + 16 + j] = ll;
        }
    }
    // V transpose
    #pragma unroll
    for (int i = 0; i < 4; i++) {
        int idx = i * 256 + tid;
        int r = idx >> 4, c4 = (idx & 15) * 4;
        float4 v = *(const float4*)(qkv + (rowg + r) * L3 + 2048 + h * 64 + c4);
        vs[r][c4] = v.x; vs[r][c4+1] = v.y; vs[r][c4+2] = v.z; vs[r][c4+3] = v.w;
    }
    __syncthreads();
    #pragma unroll
    for (int i = 0; i < 8; i++) {
        int idx = i * 256 + tid;          // 0..2047
        int d = idx >> 5, lp = idx & 31;
        uint32_t hh, ll;
        split_pack2(vs[2*lp][d], vs[2*lp+1][d], hh, ll);
        size_t o = (bh * 64 + d) * (SEQ/2) + lt * 32 + lp;
        Vh32[o] = hh; Vl32[o] = ll;
    }
}

// ---------------------------------------------------------------------------
// Split-bf16 GEMM + bias.  A[M][K] h/l row-major, B[N][K] h/l row-major (=W^T).
// CTA 128x128, BK=32, cp.async double buffer, ldmatrix fragments.
// smem stage: Ah(10240) Al(10240) Bh(10240) Bl(10240) = 40960 B; rows padded to 80 B.
// ---------------------------------------------------------------------------
#define GS 40960
__global__ __launch_bounds__(256, 2)
void gemm_bf16(const __nv_bfloat16* __restrict__ Ah, const __nv_bfloat16* __restrict__ Al,
               const __nv_bfloat16* __restrict__ Bh, const __nv_bfloat16* __restrict__ Bl,
               const float* __restrict__ bias, float* __restrict__ C,
               int M, int N, int K)
{
    extern __shared__ char smc[];
    const uint32_t smb = (uint32_t)__cvta_generic_to_shared(smc);
    const int tid = threadIdx.x, lane = tid & 31;
    const int wm = (tid >> 5) & 1, wn = tid >> 6;
    const int m0 = blockIdx.y * 128, n0 = blockIdx.x * 128;

    // staging: thread -> (tile, 2 rows, 4 chunks each)
    const int tile = tid >> 6;
    const int r2 = (tid & 63) * 2;
    const __nv_bfloat16* gt = (tile == 0) ? Ah : (tile == 1) ? Al : (tile == 2) ? Bh : Bl;
    const int gr = ((tile < 2) ? m0 : n0) + r2;
    const char* g0 = (const char*)(gt + (size_t)gr * K);
    const char* g1 = g0 + (size_t)K * 2;
    const uint32_t s0 = smb + tile * 10240 + r2 * 80;

    float acc[4][4][4];
    #pragma unroll
    for (int i = 0; i < 4; i++)
        #pragma unroll
        for (int j = 0; j < 4; j++)
            #pragma unroll
            for (int k = 0; k < 4; k++) acc[i][j][k] = 0.0f;

    const int rowA = ((lane >> 3) & 1) * 8 + (lane & 7);
    const int colA = (lane >> 4) * 16;
    const int rowB = (lane >> 4) * 8 + (lane & 7);
    const int colB = ((lane >> 3) & 1) * 16;

    const int nk = K >> 5;
    #pragma unroll
    for (int c = 0; c < 4; c++) { CP16(s0 + c*16, g0 + c*16); CP16(s0 + 80 + c*16, g1 + c*16); }
    CPCOMMIT();

    for (int kt = 0; kt < nk; kt++) {
        if (kt + 1 < nk) {
            const char* ga = g0 + (size_t)(kt + 1) * 64;
            const char* gb = g1 + (size_t)(kt + 1) * 64;
            uint32_t sa = s0 + ((kt + 1) & 1) * GS;
            #pragma unroll
            for (int c = 0; c < 4; c++) { CP16(sa + c*16, ga + c*16); CP16(sa + 80 + c*16, gb + c*16); }
        }
        CPCOMMIT();
        CPWAIT1();
        __syncthreads();
        const uint32_t st = smb + (kt & 1) * GS;

        #pragma unroll
        for (int ks = 0; ks < 2; ks++) {
            uint32_t ah[4][4], al_[4][4];
            #pragma unroll
            for (int mt = 0; mt < 4; mt++) {
                uint32_t aa = st + (uint32_t)(wm * 64 + mt * 16 + rowA) * 80 + ks * 32 + colA;
                LDSM4(ah[mt][0], ah[mt][1], ah[mt][2], ah[mt][3], aa);
                LDSM4(al_[mt][0], al_[mt][1], al_[mt][2], al_[mt][3], aa + 10240);
            }
            #pragma unroll
            for (int ntp = 0; ntp < 2; ntp++) {
                uint32_t ba = st + 20480 + (uint32_t)(wn * 32 + ntp * 16 + rowB) * 80 + ks * 32 + colB;
                uint32_t bh0, bh1, bh2, bh3, bl0, bl1, bl2, bl3;
                LDSM4(bh0, bh1, bh2, bh3, ba);
                LDSM4(bl0, bl1, bl2, bl3, ba + 10240);
                #pragma unroll
                for (int mt = 0; mt < 4; mt++) {
                    mma_bf16(acc[mt][2*ntp],   ah[mt][0], ah[mt][1], ah[mt][2], ah[mt][3], bh0, bh1);
                    mma_bf16(acc[mt][2*ntp],   ah[mt][0], ah[mt][1], ah[mt][2], ah[mt][3], bl0, bl1);
                    mma_bf16(acc[mt][2*ntp],   al_[mt][0], al_[mt][1], al_[mt][2], al_[mt][3], bh0, bh1);
                    mma_bf16(acc[mt][2*ntp+1], ah[mt][0], ah[mt][1], ah[mt][2], ah[mt][3], bh2, bh3);
                    mma_bf16(acc[mt][2*ntp+1], ah[mt][0], ah[mt][1], ah[mt][2], ah[mt][3], bl2, bl3);
                    mma_bf16(acc[mt][2*ntp+1], al_[mt][0], al_[mt][1], al_[mt][2], al_[mt][3], bh2, bh3);
                }
            }
        }
        __syncthreads();
    }

    #pragma unroll
    for (int nt = 0; nt < 4; nt++) {
        int col = n0 + wn * 32 + nt * 8 + (lane & 3) * 2;
        float2 bs = *(const float2*)&bias[col];
        #pragma unroll
        for (int mt = 0; mt < 4; mt++) {
            int r = m0 + wm * 64 + mt * 16 + (lane >> 2);
            float2 v0 = { acc[mt][nt][0] + bs.x, acc[mt][nt][1] + bs.y };
            float2 v1 = { acc[mt][nt][2] + bs.x, acc[mt][nt][3] + bs.y };
            *(float2*)&C[(size_t)r * N + col]       = v0;
            *(float2*)&C[(size_t)(r + 8) * N + col] = v1;
        }
    }
}

// ---------------------------------------------------------------------------
// Flash attention, pure-bf16 inputs, cp.async double buffer, ldmatrix frags.
// smem: Qh(18432) Ql(18432) | 2 stages of { Kh Kl Vh Vl } (9216 each) = 110592 B
// rows padded to 144 B.
// ---------------------------------------------------------------------------
#define FQ     36864
#define FSTAGE 36864
#define FSM    (FQ + 2*FSTAGE)

__global__ __launch_bounds__(256, 2)
void flash_bf16(const __nv_bfloat16* __restrict__ Qh, const __nv_bfloat16* __restrict__ Ql,
                const __nv_bfloat16* __restrict__ Kh, const __nv_bfloat16* __restrict__ Kl,
                const __nv_bfloat16* __restrict__ Vh, const __nv_bfloat16* __restrict__ Vl)
{
    extern __shared__ char smc[];
    const uint32_t smb = (uint32_t)__cvta_generic_to_shared(smc);
    const int tid = threadIdx.x, lane = tid & 31, wid = tid >> 5;
    const int qt = blockIdx.x, h = blockIdx.y, b = blockIdx.z;
    const size_t bh = (size_t)b * NH + h;

    // Q staging: one row (128B) per thread, hi/lo by tid>>7
    {
        const int qtile = tid >> 7;
        const int qr = tid & 127;
        const __nv_bfloat16* qsrc = qtile ? Ql : Qh;
        const char* gq = (const char*)(qsrc + (bh * SEQ + (size_t)qt * 128 + qr) * 64);
        uint32_t sq = smb + qtile * 18432 + qr * 144;
        #pragma unroll
        for (int c = 0; c < 8; c++) CP16(sq + c*16, gq + c*16);
    }
    // K/V staging: one row per thread
    const int tile = tid >> 6;
    const int krow = tid & 63;
    const char* gkv;
    int gstride;
    if (tile == 0)      { gkv = (const char*)(Kh + (bh * SEQ + krow) * 64); gstride = 8192; }
    else if (tile == 1) { gkv = (const char*)(Kl + (bh * SEQ + krow) * 64); gstride = 8192; }
    else if (tile == 2) { gkv = (const char*)(Vh + (bh * 64 + krow) * SEQ); gstride = 128; }
    else                { gkv = (const char*)(Vl + (bh * 64 + krow) * SEQ); gstride = 128; }
    const uint32_t skv = smb + FQ + tile * 9216 + krow * 144;
    #pragma unroll
    for (int c = 0; c < 8; c++) CP16(skv + c*16, gkv + c*16);
    CPCOMMIT();

    float s[8][4], o[8][4];
    float m0r = -INFINITY, m1r = -INFINITY, l0r = 0.0f, l1r = 0.0f;
    #pragma unroll
    for (int i = 0; i < 8; i++)
        #pragma unroll
        for (int j = 0; j < 4; j++) o[i][j] = 0.0f;

    const int rowA = ((lane >> 3) & 1) * 8 + (lane & 7);
    const int colA = (lane >> 4) * 16;
    const int rowB = (lane >> 4) * 8 + (lane & 7);
    const int colB = ((lane >> 3) & 1) * 16;

    for (int t = 0; t < SEQ / 64; t++) {
        if (t < SEQ / 64 - 1) {
            const char* gp = gkv + (size_t)(t + 1) * gstride;
            uint32_t sp = skv + ((t + 1) & 1) * FSTAGE;
            #pragma unroll
            for (int c = 0; c < 8; c++) CP16(sp + c*16, gp + c*16);
        }
        CPCOMMIT();
        CPWAIT1();
        __syncthreads();
        const uint32_t kvb = smb + FQ + (t & 1) * FSTAGE;

        // ---- S = Q @ K^T (3-term split)
        #pragma unroll
        for (int i = 0; i < 8; i++)
            #pragma unroll
            for (int j = 0; j < 4; j++) s[i][j] = 0.0f;

        #pragma unroll
        for (int ks = 0; ks < 4; ks++) {
            uint32_t qa = smb + (uint32_t)(wid * 16 + rowA) * 144 + ks * 32 + colA;
            uint32_t qh0, qh1, qh2, qh3, ql0, ql1, ql2, ql3;
            LDSM4(qh0, qh1, qh2, qh3, qa);
            LDSM4(ql0, ql1, ql2, ql3, qa + 18432);
            #pragma unroll
            for (int ntp = 0; ntp < 4; ntp++) {
                uint32_t ka = kvb + (uint32_t)(ntp * 16 + rowB) * 144 + ks * 32 + colB;
                uint32_t kh0, kh1, kh2, kh3, kl0, kl1, kl2, kl3;
                LDSM4(kh0, kh1, kh2, kh3, ka);
                LDSM4(kl0, kl1, kl2, kl3, ka + 9216);
                mma_bf16(s[2*ntp],   qh0, qh1, qh2, qh3, kh0, kh1);
                mma_bf16(s[2*ntp],   qh0, qh1, qh2, qh3, kl0, kl1);
                mma_bf16(s[2*ntp],   ql0, ql1, ql2, ql3, kh0, kh1);
                mma_bf16(s[2*ntp+1], qh0, qh1, qh2, qh3, kh2, kh3);
                mma_bf16(s[2*ntp+1], qh0, qh1, qh2, qh3, kl2, kl3);
                mma_bf16(s[2*ntp+1], ql0, ql1, ql2, ql3, kh2, kh3);
            }
        }

        // ---- online softmax
        float mx0 = -INFINITY, mx1 = -INFINITY;
        #pragma unroll
        for (int nt = 0; nt < 8; nt++) {
            mx0 = fmaxf(mx0, fmaxf(s[nt][0], s[nt][1]));
            mx1 = fmaxf(mx1, fmaxf(s[nt][2], s[nt][3]));
        }
        mx0 = fmaxf(mx0, __shfl_xor_sync(0xffffffffu, mx0, 1));
        mx0 = fmaxf(mx0, __shfl_xor_sync(0xffffffffu, mx0, 2));
        mx1 = fmaxf(mx1, __shfl_xor_sync(0xffffffffu, mx1, 1));
        mx1 = fmaxf(mx1, __shfl_xor_sync(0xffffffffu, mx1, 2));
        float mn0 = fmaxf(m0r, mx0), mn1 = fmaxf(m1r, mx1);
        float a0 = __expf(m0r - mn0), a1 = __expf(m1r - mn1);
        float sum0 = 0.0f, sum1 = 0.0f;
        #pragma unroll
        for (int nt = 0; nt < 8; nt++) {
            s[nt][0] = __expf(s[nt][0] - mn0); sum0 += s[nt][0];
            s[nt][1] = __expf(s[nt][1] - mn0); sum0 += s[nt][1];
            s[nt][2] = __expf(s[nt][2] - mn1); sum1 += s[nt][2];
            s[nt][3] = __expf(s[nt][3] - mn1); sum1 += s[nt][3];
        }
        sum0 += __shfl_xor_sync(0xffffffffu, sum0, 1);
        sum0 += __shfl_xor_sync(0xffffffffu, sum0, 2);
        sum1 += __shfl_xor_sync(0xffffffffu, sum1, 1);
        sum1 += __shfl_xor_sync(0xffffffffu, sum1, 2);
        l0r = l0r * a0 + sum0;  l1r = l1r * a1 + sum1;
        m0r = mn0;              m1r = mn1;
        #pragma unroll
        for (int dt = 0; dt < 8; dt++) {
            o[dt][0] *= a0; o[dt][1] *= a0;
            o[dt][2] *= a1; o[dt][3] *= a1;
        }

        // ---- O += P @ V (register repack of P into A-frag layout, hi/lo)
        #pragma unroll
        for (int kt = 0; kt < 4; kt++) {
            uint32_t ah0, ah1, ah2, ah3, au0, au1, au2, au3;
            split_pack2(s[2*kt][0],   s[2*kt][1],   ah0, au0);
            split_pack2(s[2*kt][2],   s[2*kt][3],   ah1, au1);
            split_pack2(s[2*kt+1][0], s[2*kt+1][1], ah2, au2);
            split_pack2(s[2*kt+1][2], s[2*kt+1][3], ah3, au3);
            #pragma unroll
            for (int dtp = 0; dtp < 4; dtp++) {
                uint32_t va = kvb + 18432 + (uint32_t)(dtp * 16 + rowB) * 144 + kt * 32 + colB;
                uint32_t vh0, vh1, vh2, vh3, vl0, vl1, vl2, vl3;
                LDSM4(vh0, vh1, vh2, vh3, va);
                LDSM4(vl0, vl1, vl2, vl3, va + 9216);
                mma_bf16(o[2*dtp],   ah0, ah1, ah2, ah3, vh0, vh1);
                mma_bf16(o[2*dtp],   ah0, ah1, ah2, ah3, vl0, vl1);
                mma_bf16(o[2*dtp],   au0, au1, au2, au3, vh0, vh1);
                mma_bf16(o[2*dtp+1], ah0, ah1, ah2, ah3, vh2, vh3);
                mma_bf16(o[2*dtp+1], ah0, ah1, ah2, ah3, vl2, vl3);
                mma_bf16(o[2*dtp+1], au0, au1, au2, au3, vh2, vh3);
            }
        }
        __syncthreads();
    }

    // ---- epilogue: normalize, split, pair-packed bf16 h/l to g_ath/g_atl
    float inv0 = 1.0f / l0r, inv1 = 1.0f / l1r;
    const size_t row = (size_t)b * SEQ + (size_t)qt * 128 + wid * 16 + (lane >> 2);
    uint32_t* oh32 = (uint32_t*)g_ath;
    uint32_t* ol32 = (uint32_t*)g_atl;
    #pragma unroll
    for (int dt = 0; dt < 8; dt++) {
        int cp = h * 32 + dt * 4 + (lane & 3);
        uint32_t hh, ll;
        split_pack2(o[dt][0] * inv0, o[dt][1] * inv0, hh, ll);
        oh32[row * 512 + cp] = hh;       ol32[row * 512 + cp] = ll;
        split_pack2(o[dt][2] * inv1, o[dt][3] * inv1, hh, ll);
        oh32[(row + 8) * 512 + cp] = hh; ol32[(row + 8) * 512 + cp] = ll;
    }
}

// ---------------------------------------------------------------------------
// Launcher
// ---------------------------------------------------------------------------
extern "C" void kernel_launch(void* const* d_in, const int* in_sizes, int n_in,
                              void* d_out, int out_size)
{
    const float* x     = (const float*)d_in[0];
    const float* w_qkv = (const float*)d_in[1];
    const float* b_qkv = (const float*)d_in[2];
    const float* w_out = (const float*)d_in[3];
    const float* b_out = (const float*)d_in[4];
    float* out = (float*)d_out;

    float* qkvp;
    __nv_bfloat16 *xh, *xl, *wqh, *wql, *woh, *wol, *Qh, *Ql, *Kh, *Kl, *Vh, *Vl, *ath, *atl;
    cudaGetSymbolAddress((void**)&qkvp, g_qkv);
    cudaGetSymbolAddress((void**)&xh, g_xh);   cudaGetSymbolAddress((void**)&xl, g_xl);
    cudaGetSymbolAddress((void**)&wqh, g_wqh); cudaGetSymbolAddress((void**)&wql, g_wql);
    cudaGetSymbolAddress((void**)&woh, g_woh); cudaGetSymbolAddress((void**)&wol, g_wol);
    cudaGetSymbolAddress((void**)&Qh, g_Qh);   cudaGetSymbolAddress((void**)&Ql, g_Ql);
    cudaGetSymbolAddress((void**)&Kh, g_Kh);   cudaGetSymbolAddress((void**)&Kl, g_Kl);
    cudaGetSymbolAddress((void**)&Vh, g_Vh);   cudaGetSymbolAddress((void**)&Vl, g_Vl);
    cudaGetSymbolAddress((void**)&ath, g_ath); cudaGetSymbolAddress((void**)&atl, g_atl);

    cudaFuncSetAttribute(gemm_bf16,  cudaFuncAttributeMaxDynamicSharedMemorySize, 2 * GS);
    cudaFuncSetAttribute(flash_bf16, cudaFuncAttributeMaxDynamicSharedMemorySize, FSM);

    // prep: weights (transpose+split), x (split)
    prep_wT<<<dim3(L3 / 32, DM / 32), 256>>>(w_qkv, wqh, wql, DM, L3);
    prep_wT<<<dim3(DM / 32, DM / 32), 256>>>(w_out, woh, wol, DM, DM);
    prep_x<<<(int)(((size_t)ROWS * DM / 2) / 256), 256>>>(x, xh, xl);

    // QKV projection (fp32 out + bias)
    gemm_bf16<<<dim3(L3 / 128, ROWS / 128), 256, 2 * GS>>>(xh, xl, wqh, wql, b_qkv, qkvp,
                                                           ROWS, L3, DM);
    // RoPE + split + V transpose
    prep_qkv<<<dim3(SEQ / 64, NH, BATCH), 256>>>(qkvp);

    // flash attention -> g_ath/g_atl (bf16 h/l)
    flash_bf16<<<dim3(SEQ / 128, NH, BATCH), 256, FSM>>>(Qh, Ql, Kh, Kl, Vh, Vl);

    // output projection
    gemm_bf16<<<dim3(DM / 128, ROWS / 128), 256, 2 * GS>>>(ath, atl, woh, wol, b_out, out,
                                                           ROWS, DM, DM);
}